// round 7
// baseline (speedup 1.0000x reference)
#include <cuda_runtime.h>
#include <cstdint>

#define UNITS   256
#define G3      768
#define NROWS   32
#define NCTA    128
#define NTHREADS 512
#define TSTEPS  191
#define WARM    64
#define HFS     260

#define L1_SLABS 33
#define L1_F4   (L1_SLABS*1536)
#define L2_F4   (64*1536)
#define TOT_F4  (L1_F4 + L2_F4)

__device__ float4 g_wts[TOT_F4];   // L1 blob | L2 blob, fragment-ordered tf32

#define SZ_HA1  (2*L1_SLABS*32*4)
#define OFF_HA1 0
#define OFF_HA2 (OFF_HA1 + 2*SZ_HA1)
#define SZ_HA2  (2*32*32*4)
#define OFF_HF1 (OFF_HA2 + SZ_HA2)
#define OFF_HF2 (OFF_HF1 + NROWS*HFS)
#define OFF_B1  (OFF_HF2 + NROWS*HFS)
#define OFF_B2  (OFF_B1 + 2*G3)
#define OFF_WD  (OFF_B2 + 2*G3)
#define OFF_BD  (OFF_WD + UNITS*5)
#define OFF_PART (OFF_BD + 8)
#define OFF_QP  (OFF_PART + 16*160)
#define SMEM_FLOATS (OFF_QP + NROWS*127)
#define SMEM_BYTES  (SMEM_FLOATS*4)

__device__ __forceinline__ float f2tf(float f){
    uint32_t r; asm("cvt.rna.tf32.f32 %0, %1;" : "=r"(r) : "f"(f));
    return __uint_as_float(r);
}
__device__ __forceinline__ void mma_t(float (&c)[4], const uint4& a, uint32_t b0, uint32_t b1){
    asm volatile(
        "mma.sync.aligned.m16n8k8.row.col.f32.tf32.tf32.f32 "
        "{%0,%1,%2,%3},{%4,%5,%6,%7},{%8,%9},{%0,%1,%2,%3};\n"
        : "+f"(c[0]), "+f"(c[1]), "+f"(c[2]), "+f"(c[3])
        : "r"(a.x), "r"(a.y), "r"(a.z), "r"(a.w), "r"(b0), "r"(b1));
}
__device__ __forceinline__ float sigf(float x){
    float e = __expf(-x); return __fdividef(1.f, 1.f + e);
}
__device__ __forceinline__ float tanhf_(float x){
    float e = __expf(2.f * x); return 1.f - __fdividef(2.f, e + 1.f);
}

#define MMA_GATE(ACC, B4, a0, a1) do {                     \
    mma_t(ACC[0][0], a0, (B4).x, (B4).y);                  \
    mma_t(ACC[1][0], a1, (B4).x, (B4).y);                  \
    mma_t(ACC[0][1], a0, (B4).z, (B4).w);                  \
    mma_t(ACC[1][1], a1, (B4).z, (B4).w);                  \
} while (0)

#define ZERO_ACC do {                                      \
    _Pragma("unroll")                                      \
    for (int m_=0;m_<2;m_++) _Pragma("unroll")             \
    for (int t_=0;t_<2;t_++) _Pragma("unroll")             \
    for (int c_=0;c_<4;c_++){                              \
        az[m_][t_][c_]=0.f; ar[m_][t_][c_]=0.f;            \
        axh[m_][t_][c_]=0.f; arh[m_][t_][c_]=0.f; }        \
} while (0)

// ---------------------------------------------------------------------------
__global__ void prep_kernel(const float* __restrict__ W1, const float* __restrict__ U1,
                            const float* __restrict__ W2, const float* __restrict__ U2){
    for (int idx = blockIdx.x*blockDim.x + threadIdx.x; idx < TOT_F4;
         idx += gridDim.x*blockDim.x){
        int li   = (idx < L1_F4) ? idx : idx - L1_F4;
        int lane = li & 31;
        int w    = (li >> 5) & 7;
        int t2   = (li >> 8) & 1;
        int g    = (li >> 9) % 3;
        int slab = (li >> 9) / 3;
        int lc = lane & 3, lr = lane >> 2;
        float v[4];
        #pragma unroll
        for (int j = 0; j < 4; j++){
            int q  = j & 1;
            int tt = t2*2 + (j >> 1);
            int col = g*256 + w*32 + tt*8 + lr;
            int kk  = lc + 4*q;
            float s;
            if (idx < L1_F4){
                if (slab < 32) s = U1[(slab*8 + kk)*G3 + col];
                else           s = (kk < 6) ? W1[kk*G3 + col] : 0.f;
            } else {
                if (slab < 32) s = W2[(slab*8 + kk)*G3 + col];
                else           s = U2[((slab-32)*8 + kk)*G3 + col];
            }
            uint32_t r; asm("cvt.rna.tf32.f32 %0, %1;" : "=r"(r) : "f"(s));
            v[j] = __uint_as_float(r);
        }
        g_wts[idx] = make_float4(v[0], v[1], v[2], v[3]);
    }
}

// ---------------------------------------------------------------------------
__global__ void __launch_bounds__(NTHREADS, 1)
gru_kernel(const float* __restrict__ inputs, const float* __restrict__ gb1,
           const float* __restrict__ gb2, const float* __restrict__ gWd,
           const float* __restrict__ gbd, float* __restrict__ out){
    extern __shared__ __align__(16) float sm[];
    float* hF1 = sm + OFF_HF1;
    float* hF2 = sm + OFF_HF2;
    float* b1s = sm + OFF_B1;
    float* b2s = sm + OFF_B2;
    float* wds = sm + OFF_WD;
    float* bds = sm + OFF_BD;
    float* part= sm + OFF_PART;
    float* qpre= sm + OFF_QP;

    const int tid  = threadIdx.x;
    const int lane = tid & 31;
    const int warp = tid >> 5;
    const int lr   = lane >> 2;
    const int lc   = lane & 3;
    const int u0   = warp * 16;
    const int row0 = blockIdx.x * NROWS;
    const int wB   = ((warp & 1) << 8) + ((warp >> 1) << 5) + lane;

    for (int i = tid; i < 2*G3;    i += NTHREADS) b1s[i] = gb1[i];
    for (int i = tid; i < 2*G3;    i += NTHREADS) b2s[i] = gb2[i];
    for (int i = tid; i < UNITS*5; i += NTHREADS) wds[i] = gWd[i];
    if (tid < 5) bds[tid] = gbd[tid];
    for (int i = tid; i < 2*SZ_HA1; i += NTHREADS) sm[OFF_HA1 + i] = 0.f;
    for (int i = tid; i < SZ_HA2;   i += NTHREADS) sm[OFF_HA2 + i] = 0.f;
    for (int i = tid; i < NROWS*HFS; i += NTHREADS){ hF1[i] = 0.f; hF2[i] = 0.f; }
    for (int i = tid; i < NROWS*127; i += NTHREADS){
        int row = i / 127, s = i % 127;
        qpre[i] = inputs[((size_t)(row0 + row)*192 + WARM + s)*6];
    }
    __syncthreads();

    // stage x_0 into buffer 0, slab 32
    if (tid < NROWS){
        int row = tid;
        const float* ip = inputs + ((size_t)(row0 + row)*192 + 0)*6;
        int m = row >> 4, r = row & 15, rl = r & 7, hi2 = r >> 3;
        #pragma unroll
        for (int k = 0; k < 6; k++){
            int lcc = k & 3, q = k >> 2;
            sm[OFF_HA1 + ((m*L1_SLABS + 32)*32 + rl*4 + lcc)*4 + hi2 + 2*q] = f2tf(ip[k]);
        }
    }
    __syncthreads();

    const uint4* hA2u = (const uint4*)(sm + OFF_HA2);
    const uint4* B1b  = ((const uint4*)g_wts) + wB;
    const uint4* B2b  = ((const uint4*)g_wts) + L1_F4 + wB;

    float az[2][2][4], ar[2][2][4], axh[2][2][4], arh[2][2][4];
    float hn[2][2][4];

    // prologue prefetch: B slab0 + A slab0 of buffer 0 (zeros)
    uint4 pbz = __ldg(B1b), pbr = __ldg(B1b + 512), pbh = __ldg(B1b + 1024);
    uint4 pa0 = ((const uint4*)(sm + OFF_HA1))[lane];
    uint4 pa1 = ((const uint4*)(sm + OFF_HA1))[L1_SLABS*32 + lane];

    for (int t = 0; t < TSTEPS; t++){
        const int p = t & 1;
        const uint4* hAr = (const uint4*)(sm + OFF_HA1 + p*SZ_HA1);       // h1_old + x_t
        float*       hWf = sm + OFF_HA1 + (1-p)*SZ_HA1;                   // h1_new target
        const uint4* hAw = (const uint4*)hWf;

        // ===== GEMM1 slabs 0..31 (h1_old; x-independent) =====
        ZERO_ACC;
        #pragma unroll 2
        for (int s = 0; s < 32; s++){
            uint4 cz = pbz, cr = pbr, ch = pbh;
            uint4 ca0 = pa0, ca1 = pa1;
            const uint4* Bn = B1b + (s+1)*1536;
            pbz = __ldg(Bn); pbr = __ldg(Bn + 512); pbh = __ldg(Bn + 1024);
            if (s < 31){
                pa0 = hAr[(s+1)*32 + lane];
                pa1 = hAr[(L1_SLABS + s+1)*32 + lane];
            }
            MMA_GATE(az,  cz, ca0, ca1);
            MMA_GATE(ar,  cr, ca0, ca1);
            MMA_GATE(arh, ch, ca0, ca1);
        }
        __syncthreads();                       // B3: x_t staged last iter now visible

        {   // ===== GEMM1 slab 32 (x_t); chain B -> GEMM2a slab 0; preload GEMM2a A
            uint4 a0 = hAr[32*32 + lane];
            uint4 a1 = hAr[(L1_SLABS + 32)*32 + lane];
            uint4 cz = pbz, cr = pbr, ch = pbh;
            const uint4* Bn = B2b + 32*1536;
            pbz = __ldg(Bn); pbr = __ldg(Bn + 512); pbh = __ldg(Bn + 1024);
            pa0 = hA2u[lane];
            pa1 = hA2u[32*32 + lane];
            MMA_GATE(az,  cz, a0, a1);
            MMA_GATE(ar,  cr, a0, a1);
            MMA_GATE(axh, ch, a0, a1);
        }

        // ---- gate 1 (state in hF1, fp32) ----
        #pragma unroll
        for (int tt = 0; tt < 2; tt++)
            #pragma unroll
            for (int cc = 0; cc < 2; cc++){
                int uc = u0 + tt*8 + 2*lc + cc;
                float bz  = b1s[uc]       + b1s[G3 + uc];
                float br  = b1s[256 + uc] + b1s[G3 + 256 + uc];
                float bxh = b1s[512 + uc];
                float brh = b1s[G3 + 512 + uc];
                #pragma unroll
                for (int m = 0; m < 2; m++)
                    #pragma unroll
                    for (int hi = 0; hi < 2; hi++){
                        int c = hi*2 + cc;
                        int row = 16*m + lr + 8*hi;
                        float z = sigf(az[m][tt][c] + bz);
                        float r = sigf(ar[m][tt][c] + br);
                        float hh = tanhf_(axh[m][tt][c] + bxh + r*(arh[m][tt][c] + brh));
                        float ho = hF1[row*HFS + uc];
                        float v  = z*ho + (1.f - z)*hh;
                        hF1[row*HFS + uc] = v;
                        hn[m][tt][c] = v;
                    }
            }
        #pragma unroll
        for (int tt = 0; tt < 2; tt++)
            #pragma unroll
            for (int cc = 0; cc < 2; cc++){
                int kc = 2*lc + cc, lcc = kc & 3, q = kc >> 2;
                #pragma unroll
                for (int m = 0; m < 2; m++)
                    #pragma unroll
                    for (int hi = 0; hi < 2; hi++)
                        hWf[((m*L1_SLABS + warp*2 + tt)*32 + lr*4 + lcc)*4
                            + hi + 2*q] = f2tf(hn[m][tt][hi*2 + cc]);
            }

        // ===== GEMM2a: h2_old @ U2 (blob slabs 32..63) =====
        ZERO_ACC;
        #pragma unroll 2
        for (int s = 0; s < 32; s++){
            uint4 cz = pbz, cr = pbr, ch = pbh;
            uint4 ca0 = pa0, ca1 = pa1;
            const uint4* Bn = (s < 31) ? (B2b + (33 + s)*1536) : B2b;
            pbz = __ldg(Bn); pbr = __ldg(Bn + 512); pbh = __ldg(Bn + 1024);
            if (s < 31){
                pa0 = hA2u[(s+1)*32 + lane];
                pa1 = hA2u[(32 + s+1)*32 + lane];
            }
            MMA_GATE(az,  cz, ca0, ca1);
            MMA_GATE(ar,  cr, ca0, ca1);
            MMA_GATE(arh, ch, ca0, ca1);
        }
        __syncthreads();                       // B1: h1_new visible

        // ===== GEMM2b: h1_new @ W2 (blob slabs 0..31) =====
        pa0 = hAw[lane];
        pa1 = hAw[L1_SLABS*32 + lane];
        #pragma unroll 2
        for (int s = 0; s < 32; s++){
            uint4 cz = pbz, cr = pbr, ch = pbh;
            uint4 ca0 = pa0, ca1 = pa1;
            const uint4* Bn = (s < 31) ? (B2b + (s+1)*1536) : B1b;
            pbz = __ldg(Bn); pbr = __ldg(Bn + 512); pbh = __ldg(Bn + 1024);
            if (s < 31){
                pa0 = hAw[(s+1)*32 + lane];
                pa1 = hAw[(L1_SLABS + s+1)*32 + lane];
            }
            MMA_GATE(az,  cz, ca0, ca1);
            MMA_GATE(ar,  cr, ca0, ca1);
            MMA_GATE(axh, ch, ca0, ca1);
        }

        // ---- gate 2 + h2 store + pred partials ----
        float ps[4][5];
        #pragma unroll
        for (int ri = 0; ri < 4; ri++)
            #pragma unroll
            for (int o = 0; o < 5; o++) ps[ri][o] = 0.f;

        #pragma unroll
        for (int tt = 0; tt < 2; tt++)
            #pragma unroll
            for (int cc = 0; cc < 2; cc++){
                int uc = u0 + tt*8 + 2*lc + cc;
                float bz  = b2s[uc]       + b2s[G3 + uc];
                float br  = b2s[256 + uc] + b2s[G3 + 256 + uc];
                float bxh = b2s[512 + uc];
                float brh = b2s[G3 + 512 + uc];
                float wdv[5];
                #pragma unroll
                for (int o = 0; o < 5; o++) wdv[o] = wds[uc*5 + o];
                #pragma unroll
                for (int m = 0; m < 2; m++)
                    #pragma unroll
                    for (int hi = 0; hi < 2; hi++){
                        int c = hi*2 + cc;
                        int row = 16*m + lr + 8*hi;
                        float z = sigf(az[m][tt][c] + bz);
                        float r = sigf(ar[m][tt][c] + br);
                        float hh = tanhf_(axh[m][tt][c] + bxh + r*(arh[m][tt][c] + brh));
                        float ho = hF2[row*HFS + uc];
                        float v  = z*ho + (1.f - z)*hh;
                        hF2[row*HFS + uc] = v;
                        hn[m][tt][c] = v;
                        int ri = 2*m + hi;
                        #pragma unroll
                        for (int o = 0; o < 5; o++) ps[ri][o] += v * wdv[o];
                    }
            }
        #pragma unroll
        for (int tt = 0; tt < 2; tt++)
            #pragma unroll
            for (int cc = 0; cc < 2; cc++){
                int kc = 2*lc + cc, lcc = kc & 3, q = kc >> 2;
                #pragma unroll
                for (int m = 0; m < 2; m++)
                    #pragma unroll
                    for (int hi = 0; hi < 2; hi++)
                        sm[OFF_HA2 + ((m*32 + warp*2 + tt)*32 + lr*4 + lcc)*4
                           + hi + 2*q] = f2tf(hn[m][tt][hi*2 + cc]);
            }
        #pragma unroll
        for (int ri = 0; ri < 4; ri++)
            #pragma unroll
            for (int o = 0; o < 5; o++){
                ps[ri][o] += __shfl_xor_sync(0xffffffffu, ps[ri][o], 1);
                ps[ri][o] += __shfl_xor_sync(0xffffffffu, ps[ri][o], 2);
            }
        if (lc == 0){
            #pragma unroll
            for (int ri = 0; ri < 4; ri++)
                #pragma unroll
                for (int o = 0; o < 5; o++)
                    part[warp*160 + (lr + 8*ri)*5 + o] = ps[ri][o];
        }
        __syncthreads();                       // B2: part + h2 + h1_new all visible

        // ---- tail (overlaps next GEMM1 slabs 0..31): reduce, out, x_{t+1} ----
        if (tid < 160){
            int row = tid / 5, o = tid % 5;
            float s = bds[o];
            #pragma unroll
            for (int w = 0; w < 16; w++) s += part[w*160 + tid];
            int grow = row0 + row;
            int tout = (t < WARM) ? t : t + 1;
            out[(size_t)grow*960 + tout*5 + o] = s;
            if (t == WARM - 1) out[(size_t)grow*960 + WARM*5 + o] = s;
            if (t + 1 >= WARM && t + 1 < TSTEPS){
                int k = o + 1;
                int m = row >> 4, r = row & 15, rl = r & 7, hi2 = r >> 3;
                int lcc = k & 3, q = k >> 2;
                hWf[((m*L1_SLABS + 32)*32 + rl*4 + lcc)*4 + hi2 + 2*q] = f2tf(s);
            }
        }
        if (tid < NROWS && t + 1 < TSTEPS){
            int row = tid;
            int m = row >> 4, r = row & 15, rl = r & 7, hi2 = r >> 3;
            if (t + 1 < WARM){
                const float* ip = inputs + ((size_t)(row0 + row)*192 + (t + 1))*6;
                #pragma unroll
                for (int k = 0; k < 6; k++){
                    int lcc = k & 3, q = k >> 2;
                    hWf[((m*L1_SLABS + 32)*32 + rl*4 + lcc)*4 + hi2 + 2*q] = f2tf(ip[k]);
                }
            } else {
                float qv = qpre[row*127 + (t + 1 - WARM)];
                hWf[((m*L1_SLABS + 32)*32 + rl*4 + 0)*4 + hi2] = f2tf(qv);
            }
        }
        // preload A slab 0 of next GEMM1 (h1_new, visible since B1; slab != 32)
        pa0 = hAw[lane];
        pa1 = hAw[L1_SLABS*32 + lane];
    }
}

// ---------------------------------------------------------------------------
extern "C" void kernel_launch(void* const* d_in, const int* in_sizes, int n_in,
                              void* d_out, int out_size) {
    (void)in_sizes; (void)n_in; (void)out_size;
    const float* inputs = (const float*)d_in[0];
    const float* W1 = (const float*)d_in[1];
    const float* U1 = (const float*)d_in[2];
    const float* b1 = (const float*)d_in[3];
    const float* W2 = (const float*)d_in[4];
    const float* U2 = (const float*)d_in[5];
    const float* b2 = (const float*)d_in[6];
    const float* Wd = (const float*)d_in[7];
    const float* bd = (const float*)d_in[8];
    float* out = (float*)d_out;

    cudaFuncSetAttribute(gru_kernel, cudaFuncAttributeMaxDynamicSharedMemorySize,
                         SMEM_BYTES);
    prep_kernel<<<(TOT_F4 + 255)/256, 256>>>(W1, U1, W2, U2);
    gru_kernel<<<NCTA, NTHREADS, SMEM_BYTES>>>(inputs, b1, b2, Wd, bd, out);
}

// round 8
// speedup vs baseline: 1.7823x; 1.7823x over previous
#include <cuda_runtime.h>
#include <cuda_fp16.h>
#include <cstdint>

#define UNITS   256
#define G3      768
#define NROWS   32
#define NCTA    128
#define NTHREADS 512
#define TSTEPS  191
#define WARM    64
#define HFS     260

#define L1_SLABS 17              // 16 x k16 (U1) + 1 x-slab (W1 padded)
#define L2_SLABS 32              // 16 (W2) + 16 (U2)
#define L1_U4   (L1_SLABS*1536)
#define L2_U4   (L2_SLABS*1536)
#define TOT_U4  (L1_U4 + L2_U4)

__device__ uint4 g_wts[TOT_U4];  // fp16 blobs, fragment-ordered for m16n8k16

// ---- smem layout (float / b32 offsets) ----
#define SZ_HA1  (2*L1_SLABS*32*4)            // 4352 b32 per buffer
#define OFF_HA1 0
#define OFF_HA2 (OFF_HA1 + 2*SZ_HA1)
#define SZ_HA2  (2*16*32*4)                  // 4096 b32
#define OFF_HF1 (OFF_HA2 + SZ_HA2)
#define OFF_HF2 (OFF_HF1 + NROWS*HFS)
#define OFF_B1  (OFF_HF2 + NROWS*HFS)
#define OFF_B2  (OFF_B1 + 2*G3)
#define OFF_WD  (OFF_B2 + 2*G3)
#define OFF_BD  (OFF_WD + UNITS*5)
#define OFF_PART (OFF_BD + 8)
#define OFF_QP  (OFF_PART + 16*160)
#define SMEM_FLOATS (OFF_QP + NROWS*127)
#define SMEM_BYTES  (SMEM_FLOATS*4)

__device__ __forceinline__ uint32_t pack2(float lo, float hi){
    __half2 h = __floats2half2_rn(lo, hi);
    return *(uint32_t*)&h;
}

__device__ __forceinline__ void mma_h(float (&c)[4], const uint4& a, uint32_t b0, uint32_t b1){
    asm volatile(
        "mma.sync.aligned.m16n8k16.row.col.f32.f16.f16.f32 "
        "{%0,%1,%2,%3},{%4,%5,%6,%7},{%8,%9},{%0,%1,%2,%3};\n"
        : "+f"(c[0]), "+f"(c[1]), "+f"(c[2]), "+f"(c[3])
        : "r"(a.x), "r"(a.y), "r"(a.z), "r"(a.w), "r"(b0), "r"(b1));
}
__device__ __forceinline__ float sigf(float x){
    float e = __expf(-x); return __fdividef(1.f, 1.f + e);
}
__device__ __forceinline__ float tanhf_(float x){
    float e = __expf(2.f * x); return 1.f - __fdividef(2.f, e + 1.f);
}

// One gate, one k16 slab: B uint4 = {tt0:b0, tt0:b1, tt1:b0, tt1:b1}
#define MMA_GATE(ACC, B4, a0, a1) do {                     \
    mma_h(ACC[0][0], a0, (B4).x, (B4).y);                  \
    mma_h(ACC[1][0], a1, (B4).x, (B4).y);                  \
    mma_h(ACC[0][1], a0, (B4).z, (B4).w);                  \
    mma_h(ACC[1][1], a1, (B4).z, (B4).w);                  \
} while (0)

#define ZERO_ACC do {                                      \
    _Pragma("unroll")                                      \
    for (int m_=0;m_<2;m_++) _Pragma("unroll")             \
    for (int t_=0;t_<2;t_++) _Pragma("unroll")             \
    for (int c_=0;c_<4;c_++){                              \
        az[m_][t_][c_]=0.f; ar[m_][t_][c_]=0.f;            \
        axh[m_][t_][c_]=0.f; arh[m_][t_][c_]=0.f; }        \
} while (0)

// ---------------------------------------------------------------------------
// prep: fp16 fragment-order blobs. uint4 idx = slab*1536 + g*512 + t2*256
//   + w*32 + lane. Component j: tt = 2*t2 + (j>>1), q = j&1,
//   col = g*256 + w*32 + tt*8 + (lane>>2), k_local = 2*(lane&3) + 8*q (+1 hi).
__global__ void prep_kernel(const float* __restrict__ W1, const float* __restrict__ U1,
                            const float* __restrict__ W2, const float* __restrict__ U2){
    for (int idx = blockIdx.x*blockDim.x + threadIdx.x; idx < TOT_U4;
         idx += gridDim.x*blockDim.x){
        int li   = (idx < L1_U4) ? idx : idx - L1_U4;
        int lane = li & 31;
        int w    = (li >> 5) & 7;
        int t2   = (li >> 8) & 1;
        int g    = (li >> 9) % 3;
        int slab = (li >> 9) / 3;
        int lc = lane & 3, lr = lane >> 2;
        uint32_t v[4];
        #pragma unroll
        for (int j = 0; j < 4; j++){
            int q  = j & 1;
            int tt = t2*2 + (j >> 1);
            int col = g*256 + w*32 + tt*8 + lr;
            int kl  = 2*lc + 8*q;
            float s0, s1;
            if (idx < L1_U4){
                if (slab < 16){
                    s0 = U1[(slab*16 + kl)*G3 + col];
                    s1 = U1[(slab*16 + kl + 1)*G3 + col];
                } else {
                    s0 = (kl     < 6) ? W1[kl*G3 + col]       : 0.f;
                    s1 = (kl + 1 < 6) ? W1[(kl + 1)*G3 + col] : 0.f;
                }
            } else {
                if (slab < 16){
                    s0 = W2[(slab*16 + kl)*G3 + col];
                    s1 = W2[(slab*16 + kl + 1)*G3 + col];
                } else {
                    s0 = U2[((slab-16)*16 + kl)*G3 + col];
                    s1 = U2[((slab-16)*16 + kl + 1)*G3 + col];
                }
            }
            v[j] = pack2(s0, s1);
        }
        g_wts[idx] = make_uint4(v[0], v[1], v[2], v[3]);
    }
}

// ---------------------------------------------------------------------------
__global__ void __launch_bounds__(NTHREADS, 1)
gru_kernel(const float* __restrict__ inputs, const float* __restrict__ gb1,
           const float* __restrict__ gb2, const float* __restrict__ gWd,
           const float* __restrict__ gbd, float* __restrict__ out){
    extern __shared__ __align__(16) float sm[];
    float* hF1 = sm + OFF_HF1;
    float* hF2 = sm + OFF_HF2;
    float* b1s = sm + OFF_B1;
    float* b2s = sm + OFF_B2;
    float* wds = sm + OFF_WD;
    float* bds = sm + OFF_BD;
    float* part= sm + OFF_PART;
    float* qpre= sm + OFF_QP;

    const int tid  = threadIdx.x;
    const int lane = tid & 31;
    const int warp = tid >> 5;
    const int lr   = lane >> 2;
    const int lc   = lane & 3;
    const int u0   = warp * 16;
    const int row0 = blockIdx.x * NROWS;
    const int wB   = ((warp & 1) << 8) + ((warp >> 1) << 5) + lane;

    for (int i = tid; i < 2*G3;    i += NTHREADS) b1s[i] = gb1[i];
    for (int i = tid; i < 2*G3;    i += NTHREADS) b2s[i] = gb2[i];
    for (int i = tid; i < UNITS*5; i += NTHREADS) wds[i] = gWd[i];
    if (tid < 5) bds[tid] = gbd[tid];
    for (int i = tid; i < 2*SZ_HA1; i += NTHREADS) sm[OFF_HA1 + i] = 0.f;
    for (int i = tid; i < SZ_HA2;   i += NTHREADS) sm[OFF_HA2 + i] = 0.f;
    for (int i = tid; i < NROWS*HFS; i += NTHREADS){ hF1[i] = 0.f; hF2[i] = 0.f; }
    for (int i = tid; i < NROWS*127; i += NTHREADS){
        int row = i / 127, s = i % 127;
        qpre[i] = inputs[((size_t)(row0 + row)*192 + WARM + s)*6];
    }
    __syncthreads();

    // stage x_0 into buffer 0, slab 16 (halves)
    if (tid < NROWS){
        int row = tid;
        const float* ip = inputs + ((size_t)(row0 + row)*192 + 0)*6;
        int m = row >> 4, rr = row & 15, hh = rr >> 3, rl = rr & 7;
        __half* hp = (__half*)(sm + OFF_HA1);
        #pragma unroll
        for (int k = 0; k < 6; k++)
            hp[(((m*L1_SLABS + 16)*32 + rl*4 + (k >> 1))*4 + hh)*2 + (k & 1)]
                = __float2half_rn(ip[k]);
    }
    __syncthreads();

    const uint4* hA2u = (const uint4*)(sm + OFF_HA2);
    const uint4* B1b  = g_wts + wB;
    const uint4* B2b  = g_wts + L1_U4 + wB;

    float az[2][2][4], ar[2][2][4], axh[2][2][4], arh[2][2][4];
    float hn[2][2][4];

    uint4 pbz = __ldg(B1b), pbr = __ldg(B1b + 512), pbh = __ldg(B1b + 1024);

    for (int t = 0; t < TSTEPS; t++){
        const int p = t & 1;
        const uint4* hAr = (const uint4*)(sm + OFF_HA1 + p*SZ_HA1);
        float*       hWf = sm + OFF_HA1 + (1-p)*SZ_HA1;
        const uint4* hAw = (const uint4*)hWf;

        // ===== GEMM1: h1_old @ U1 (slabs 0..15) + x (slab 16) =====
        ZERO_ACC;
        #pragma unroll 4
        for (int s = 0; s < 16; s++){
            uint4 a0 = hAr[s*32 + lane];
            uint4 a1 = hAr[(L1_SLABS + s)*32 + lane];
            uint4 cz = pbz, cr = pbr, ch = pbh;
            const uint4* Bn = B1b + (s+1)*1536;
            pbz = __ldg(Bn); pbr = __ldg(Bn + 512); pbh = __ldg(Bn + 1024);
            MMA_GATE(az,  cz, a0, a1);
            MMA_GATE(ar,  cr, a0, a1);
            MMA_GATE(arh, ch, a0, a1);
        }
        {   // x slab; chain prefetch -> GEMM2a first slab (L2 blob 16)
            uint4 a0 = hAr[16*32 + lane];
            uint4 a1 = hAr[(L1_SLABS + 16)*32 + lane];
            uint4 cz = pbz, cr = pbr, ch = pbh;
            const uint4* Bn = B2b + 16*1536;
            pbz = __ldg(Bn); pbr = __ldg(Bn + 512); pbh = __ldg(Bn + 1024);
            MMA_GATE(az,  cz, a0, a1);
            MMA_GATE(ar,  cr, a0, a1);
            MMA_GATE(axh, ch, a0, a1);
        }

        // ---- gate 1 (fp32 state) ----
        #pragma unroll
        for (int tt = 0; tt < 2; tt++)
            #pragma unroll
            for (int cc = 0; cc < 2; cc++){
                int uc = u0 + tt*8 + 2*lc + cc;
                float bz  = b1s[uc]       + b1s[G3 + uc];
                float br  = b1s[256 + uc] + b1s[G3 + 256 + uc];
                float bxh = b1s[512 + uc];
                float brh = b1s[G3 + 512 + uc];
                #pragma unroll
                for (int m = 0; m < 2; m++)
                    #pragma unroll
                    for (int hi = 0; hi < 2; hi++){
                        int c = hi*2 + cc;
                        int row = 16*m + lr + 8*hi;
                        float z = sigf(az[m][tt][c] + bz);
                        float r = sigf(ar[m][tt][c] + br);
                        float hh = tanhf_(axh[m][tt][c] + bxh + r*(arh[m][tt][c] + brh));
                        float ho = hF1[row*HFS + uc];
                        float v  = z*ho + (1.f - z)*hh;
                        hF1[row*HFS + uc] = v;
                        hn[m][tt][c] = v;
                    }
            }
        // store h1_new (fp16 pairs) into write buffer
        {
            uint32_t* wp = (uint32_t*)hWf;
            #pragma unroll
            for (int m = 0; m < 2; m++)
                #pragma unroll
                for (int tt = 0; tt < 2; tt++)
                    #pragma unroll
                    for (int hi = 0; hi < 2; hi++)
                        wp[((m*L1_SLABS + warp)*32 + lr*4 + lc)*4 + tt*2 + hi]
                            = pack2(hn[m][tt][hi*2], hn[m][tt][hi*2 + 1]);
        }

        // ===== GEMM2a: h2_old @ U2 (L2 blob slabs 16..31) =====
        ZERO_ACC;
        #pragma unroll 4
        for (int s = 0; s < 16; s++){
            uint4 a0 = hA2u[s*32 + lane];
            uint4 a1 = hA2u[(16 + s)*32 + lane];
            uint4 cz = pbz, cr = pbr, ch = pbh;
            const uint4* Bn = (s < 15) ? (B2b + (17 + s)*1536) : B2b;
            pbz = __ldg(Bn); pbr = __ldg(Bn + 512); pbh = __ldg(Bn + 1024);
            MMA_GATE(az,  cz, a0, a1);
            MMA_GATE(ar,  cr, a0, a1);
            MMA_GATE(arh, ch, a0, a1);
        }
        __syncthreads();                       // B1: h1_new visible

        // ===== GEMM2b: h1_new @ W2 (L2 blob slabs 0..15) =====
        #pragma unroll 4
        for (int s = 0; s < 16; s++){
            uint4 a0 = hAw[s*32 + lane];
            uint4 a1 = hAw[(L1_SLABS + s)*32 + lane];
            uint4 cz = pbz, cr = pbr, ch = pbh;
            const uint4* Bn = (s < 15) ? (B2b + (s+1)*1536) : B1b;
            pbz = __ldg(Bn); pbr = __ldg(Bn + 512); pbh = __ldg(Bn + 1024);
            MMA_GATE(az,  cz, a0, a1);
            MMA_GATE(ar,  cr, a0, a1);
            MMA_GATE(axh, ch, a0, a1);
        }

        // ---- gate 2 + h2 store + pred partials ----
        float ps[4][5];
        #pragma unroll
        for (int ri = 0; ri < 4; ri++)
            #pragma unroll
            for (int o = 0; o < 5; o++) ps[ri][o] = 0.f;

        #pragma unroll
        for (int tt = 0; tt < 2; tt++)
            #pragma unroll
            for (int cc = 0; cc < 2; cc++){
                int uc = u0 + tt*8 + 2*lc + cc;
                float bz  = b2s[uc]       + b2s[G3 + uc];
                float br  = b2s[256 + uc] + b2s[G3 + 256 + uc];
                float bxh = b2s[512 + uc];
                float brh = b2s[G3 + 512 + uc];
                float wdv[5];
                #pragma unroll
                for (int o = 0; o < 5; o++) wdv[o] = wds[uc*5 + o];
                #pragma unroll
                for (int m = 0; m < 2; m++)
                    #pragma unroll
                    for (int hi = 0; hi < 2; hi++){
                        int c = hi*2 + cc;
                        int row = 16*m + lr + 8*hi;
                        float z = sigf(az[m][tt][c] + bz);
                        float r = sigf(ar[m][tt][c] + br);
                        float hh = tanhf_(axh[m][tt][c] + bxh + r*(arh[m][tt][c] + brh));
                        float ho = hF2[row*HFS + uc];
                        float v  = z*ho + (1.f - z)*hh;
                        hF2[row*HFS + uc] = v;
                        hn[m][tt][c] = v;
                        int ri = 2*m + hi;
                        #pragma unroll
                        for (int o = 0; o < 5; o++) ps[ri][o] += v * wdv[o];
                    }
            }
        {
            uint32_t* wp = (uint32_t*)(sm + OFF_HA2);
            #pragma unroll
            for (int m = 0; m < 2; m++)
                #pragma unroll
                for (int tt = 0; tt < 2; tt++)
                    #pragma unroll
                    for (int hi = 0; hi < 2; hi++)
                        wp[((m*16 + warp)*32 + lr*4 + lc)*4 + tt*2 + hi]
                            = pack2(hn[m][tt][hi*2], hn[m][tt][hi*2 + 1]);
        }
        #pragma unroll
        for (int ri = 0; ri < 4; ri++)
            #pragma unroll
            for (int o = 0; o < 5; o++){
                ps[ri][o] += __shfl_xor_sync(0xffffffffu, ps[ri][o], 1);
                ps[ri][o] += __shfl_xor_sync(0xffffffffu, ps[ri][o], 2);
            }
        if (lc == 0){
            #pragma unroll
            for (int ri = 0; ri < 4; ri++)
                #pragma unroll
                for (int o = 0; o < 5; o++)
                    part[warp*160 + (lr + 8*ri)*5 + o] = ps[ri][o];
        }
        __syncthreads();                       // B2

        // ---- tail: reduce, output, stage x_{t+1} ----
        if (tid < 160){
            int row = tid / 5, o = tid % 5;
            float s = bds[o];
            #pragma unroll
            for (int w = 0; w < 16; w++) s += part[w*160 + tid];
            int grow = row0 + row;
            int tout = (t < WARM) ? t : t + 1;
            out[(size_t)grow*960 + tout*5 + o] = s;
            if (t == WARM - 1) out[(size_t)grow*960 + WARM*5 + o] = s;
            if (t + 1 >= WARM && t + 1 < TSTEPS){
                int k = o + 1;
                int m = row >> 4, rr = row & 15, hh = rr >> 3, rl = rr & 7;
                __half* hp = (__half*)hWf;
                hp[(((m*L1_SLABS + 16)*32 + rl*4 + (k >> 1))*4 + hh)*2 + (k & 1)]
                    = __float2half_rn(s);
            }
        }
        if (tid < NROWS && t + 1 < TSTEPS){
            int row = tid;
            int m = row >> 4, rr = row & 15, hh = rr >> 3, rl = rr & 7;
            __half* hp = (__half*)hWf;
            if (t + 1 < WARM){
                const float* ip = inputs + ((size_t)(row0 + row)*192 + (t + 1))*6;
                #pragma unroll
                for (int k = 0; k < 6; k++)
                    hp[(((m*L1_SLABS + 16)*32 + rl*4 + (k >> 1))*4 + hh)*2 + (k & 1)]
                        = __float2half_rn(ip[k]);
            } else {
                float qv = qpre[row*127 + (t + 1 - WARM)];
                hp[(((m*L1_SLABS + 16)*32 + rl*4)*4 + hh)*2] = __float2half_rn(qv);
            }
        }
        __syncthreads();                       // B3: x_{t+1} visible
    }
}

// ---------------------------------------------------------------------------
extern "C" void kernel_launch(void* const* d_in, const int* in_sizes, int n_in,
                              void* d_out, int out_size) {
    (void)in_sizes; (void)n_in; (void)out_size;
    const float* inputs = (const float*)d_in[0];
    const float* W1 = (const float*)d_in[1];
    const float* U1 = (const float*)d_in[2];
    const float* b1 = (const float*)d_in[3];
    const float* W2 = (const float*)d_in[4];
    const float* U2 = (const float*)d_in[5];
    const float* b2 = (const float*)d_in[6];
    const float* Wd = (const float*)d_in[7];
    const float* bd = (const float*)d_in[8];
    float* out = (float*)d_out;

    cudaFuncSetAttribute(gru_kernel, cudaFuncAttributeMaxDynamicSharedMemorySize,
                         SMEM_BYTES);
    prep_kernel<<<(TOT_U4 + 255)/256, 256>>>(W1, U1, W2, U2);
    gru_kernel<<<NCTA, NTHREADS, SMEM_BYTES>>>(inputs, b1, b2, Wd, bd, out);
}

// round 9
// speedup vs baseline: 1.8355x; 1.0299x over previous
#include <cuda_runtime.h>
#include <cuda_fp16.h>
#include <cstdint>

#define UNITS   256
#define G3      768
#define NROWS   32
#define NCTA    128
#define NTHREADS 512
#define TSTEPS  191
#define WARM    64
#define HFS     260

#define L1_SLABS 17
#define L2_SLABS 32
#define L1_U4   (L1_SLABS*1536)
#define L2_U4   (L2_SLABS*1536)
#define TOT_U4  (L1_U4 + L2_U4)

__device__ uint4 g_wts[TOT_U4];  // fp16 blobs, fragment-ordered for m16n8k16

#define SZ_HA1  (2*L1_SLABS*32*4)
#define OFF_HA1 0
#define OFF_HA2 (OFF_HA1 + 2*SZ_HA1)
#define SZ_HA2  (2*16*32*4)
#define OFF_HF1 (OFF_HA2 + SZ_HA2)
#define OFF_HF2 (OFF_HF1 + NROWS*HFS)
#define OFF_B1  (OFF_HF2 + NROWS*HFS)
#define OFF_B2  (OFF_B1 + 2*G3)
#define OFF_WD  (OFF_B2 + 2*G3)
#define OFF_BD  (OFF_WD + UNITS*5)
#define OFF_PART (OFF_BD + 8)
#define OFF_QP  (OFF_PART + 16*160)
#define SMEM_FLOATS (OFF_QP + NROWS*127)
#define SMEM_BYTES  (SMEM_FLOATS*4)

__device__ __forceinline__ uint32_t pack2(float lo, float hi){
    __half2 h = __floats2half2_rn(lo, hi);
    return *(uint32_t*)&h;
}
__device__ __forceinline__ void mma_h(float (&c)[4], const uint4& a, uint32_t b0, uint32_t b1){
    asm volatile(
        "mma.sync.aligned.m16n8k16.row.col.f32.f16.f16.f32 "
        "{%0,%1,%2,%3},{%4,%5,%6,%7},{%8,%9},{%0,%1,%2,%3};\n"
        : "+f"(c[0]), "+f"(c[1]), "+f"(c[2]), "+f"(c[3])
        : "r"(a.x), "r"(a.y), "r"(a.z), "r"(a.w), "r"(b0), "r"(b1));
}
__device__ __forceinline__ float sigf(float x){
    float e = __expf(-x); return __fdividef(1.f, 1.f + e);
}
__device__ __forceinline__ float tanhf_(float x){
    float e = __expf(2.f * x); return 1.f - __fdividef(2.f, e + 1.f);
}

#define MMA_GATE(ACC, B4, a0, a1) do {                     \
    mma_h(ACC[0][0], a0, (B4).x, (B4).y);                  \
    mma_h(ACC[1][0], a1, (B4).x, (B4).y);                  \
    mma_h(ACC[0][1], a0, (B4).z, (B4).w);                  \
    mma_h(ACC[1][1], a1, (B4).z, (B4).w);                  \
} while (0)

#define ZERO_ACC do {                                      \
    _Pragma("unroll")                                      \
    for (int m_=0;m_<2;m_++) _Pragma("unroll")             \
    for (int t_=0;t_<2;t_++) _Pragma("unroll")             \
    for (int c_=0;c_<4;c_++){                              \
        az[m_][t_][c_]=0.f; ar[m_][t_][c_]=0.f;            \
        axh[m_][t_][c_]=0.f; arh[m_][t_][c_]=0.f; }        \
} while (0)

// consume oldest B set, shift, load from Bn
#define PF_STEP(CZ,CR,CH,Bn) \
    uint4 CZ = pbz0, CR = pbr0, CH = pbh0;                  \
    pbz0 = pbz1; pbr0 = pbr1; pbh0 = pbh1;                  \
    pbz1 = __ldg(Bn); pbr1 = __ldg((Bn)+512); pbh1 = __ldg((Bn)+1024);

// ---------------------------------------------------------------------------
__global__ void prep_kernel(const float* __restrict__ W1, const float* __restrict__ U1,
                            const float* __restrict__ W2, const float* __restrict__ U2){
    for (int idx = blockIdx.x*blockDim.x + threadIdx.x; idx < TOT_U4;
         idx += gridDim.x*blockDim.x){
        int li   = (idx < L1_U4) ? idx : idx - L1_U4;
        int lane = li & 31;
        int w    = (li >> 5) & 7;
        int t2   = (li >> 8) & 1;
        int g    = (li >> 9) % 3;
        int slab = (li >> 9) / 3;
        int lc = lane & 3, lr = lane >> 2;
        uint32_t v[4];
        #pragma unroll
        for (int j = 0; j < 4; j++){
            int q  = j & 1;
            int tt = t2*2 + (j >> 1);
            int col = g*256 + w*32 + tt*8 + lr;
            int kl  = 2*lc + 8*q;
            float s0, s1;
            if (idx < L1_U4){
                if (slab < 16){
                    s0 = U1[(slab*16 + kl)*G3 + col];
                    s1 = U1[(slab*16 + kl + 1)*G3 + col];
                } else {
                    s0 = (kl     < 6) ? W1[kl*G3 + col]       : 0.f;
                    s1 = (kl + 1 < 6) ? W1[(kl + 1)*G3 + col] : 0.f;
                }
            } else {
                if (slab < 16){
                    s0 = W2[(slab*16 + kl)*G3 + col];
                    s1 = W2[(slab*16 + kl + 1)*G3 + col];
                } else {
                    s0 = U2[((slab-16)*16 + kl)*G3 + col];
                    s1 = U2[((slab-16)*16 + kl + 1)*G3 + col];
                }
            }
            v[j] = pack2(s0, s1);
        }
        g_wts[idx] = make_uint4(v[0], v[1], v[2], v[3]);
    }
}

// ---------------------------------------------------------------------------
__global__ void __launch_bounds__(NTHREADS, 1)
gru_kernel(const float* __restrict__ inputs, const float* __restrict__ gb1,
           const float* __restrict__ gb2, const float* __restrict__ gWd,
           const float* __restrict__ gbd, float* __restrict__ out){
    extern __shared__ __align__(16) float sm[];
    float* hF1 = sm + OFF_HF1;
    float* hF2 = sm + OFF_HF2;
    float* b1s = sm + OFF_B1;
    float* b2s = sm + OFF_B2;
    float* wds = sm + OFF_WD;
    float* bds = sm + OFF_BD;
    float* part= sm + OFF_PART;
    float* qpre= sm + OFF_QP;

    const int tid  = threadIdx.x;
    const int lane = tid & 31;
    const int warp = tid >> 5;
    const int lr   = lane >> 2;
    const int lc   = lane & 3;
    const int u0   = warp * 16;
    const int row0 = blockIdx.x * NROWS;
    const int wB   = ((warp & 1) << 8) + ((warp >> 1) << 5) + lane;

    for (int i = tid; i < 2*G3;    i += NTHREADS) b1s[i] = gb1[i];
    for (int i = tid; i < 2*G3;    i += NTHREADS) b2s[i] = gb2[i];
    for (int i = tid; i < UNITS*5; i += NTHREADS) wds[i] = gWd[i];
    if (tid < 5) bds[tid] = gbd[tid];
    for (int i = tid; i < 2*SZ_HA1; i += NTHREADS) sm[OFF_HA1 + i] = 0.f;
    for (int i = tid; i < SZ_HA2;   i += NTHREADS) sm[OFF_HA2 + i] = 0.f;
    for (int i = tid; i < NROWS*HFS; i += NTHREADS){ hF1[i] = 0.f; hF2[i] = 0.f; }
    for (int i = tid; i < NROWS*127; i += NTHREADS){
        int row = i / 127, s = i % 127;
        qpre[i] = inputs[((size_t)(row0 + row)*192 + WARM + s)*6];
    }
    __syncthreads();

    if (tid < NROWS){
        int row = tid;
        const float* ip = inputs + ((size_t)(row0 + row)*192 + 0)*6;
        int m = row >> 4, rr = row & 15, hh = rr >> 3, rl = rr & 7;
        __half* hp = (__half*)(sm + OFF_HA1);
        #pragma unroll
        for (int k = 0; k < 6; k++)
            hp[(((m*L1_SLABS + 16)*32 + rl*4 + (k >> 1))*4 + hh)*2 + (k & 1)]
                = __float2half_rn(ip[k]);
    }
    __syncthreads();

    const uint4* hA2u = (const uint4*)(sm + OFF_HA2);
    const uint4* B1b  = g_wts + wB;
    const uint4* B2b  = g_wts + L1_U4 + wB;

    float az[2][2][4], ar[2][2][4], axh[2][2][4], arh[2][2][4];
    float hn[2][2][4];

    // depth-2 prologue: slabs 0 and 1 of GEMM1
    uint4 pbz0 = __ldg(B1b),        pbr0 = __ldg(B1b + 512),        pbh0 = __ldg(B1b + 1024);
    uint4 pbz1 = __ldg(B1b + 1536), pbr1 = __ldg(B1b + 1536 + 512), pbh1 = __ldg(B1b + 1536 + 1024);

    for (int t = 0; t < TSTEPS; t++){
        const int p = t & 1;
        const uint4* hAr = (const uint4*)(sm + OFF_HA1 + p*SZ_HA1);
        float*       hWf = sm + OFF_HA1 + (1-p)*SZ_HA1;
        const uint4* hAw = (const uint4*)hWf;

        // ===== GEMM1: h1_old @ U1 (slabs 0..15) + x (slab 16) =====
        ZERO_ACC;
        #pragma unroll 4
        for (int s = 0; s < 16; s++){
            uint4 a0 = hAr[s*32 + lane];
            uint4 a1 = hAr[(L1_SLABS + s)*32 + lane];
            const uint4* Bn = (s <= 14) ? (B1b + (s+2)*1536) : (B2b + 16*1536);
            PF_STEP(cz, cr, ch, Bn);
            MMA_GATE(az,  cz, a0, a1);
            MMA_GATE(ar,  cr, a0, a1);
            MMA_GATE(arh, ch, a0, a1);
        }
        {   // x slab (chain i=16: prefetch seq[18] = G2a slab 17 of L2 blob)
            uint4 a0 = hAr[16*32 + lane];
            uint4 a1 = hAr[(L1_SLABS + 16)*32 + lane];
            const uint4* Bn = B2b + 17*1536;
            PF_STEP(cz, cr, ch, Bn);
            MMA_GATE(az,  cz, a0, a1);
            MMA_GATE(ar,  cr, a0, a1);
            MMA_GATE(axh, ch, a0, a1);
        }

        // ---- gate 1 ----
        #pragma unroll
        for (int tt = 0; tt < 2; tt++)
            #pragma unroll
            for (int cc = 0; cc < 2; cc++){
                int uc = u0 + tt*8 + 2*lc + cc;
                float bz  = b1s[uc]       + b1s[G3 + uc];
                float br  = b1s[256 + uc] + b1s[G3 + 256 + uc];
                float bxh = b1s[512 + uc];
                float brh = b1s[G3 + 512 + uc];
                #pragma unroll
                for (int m = 0; m < 2; m++)
                    #pragma unroll
                    for (int hi = 0; hi < 2; hi++){
                        int c = hi*2 + cc;
                        int row = 16*m + lr + 8*hi;
                        float z = sigf(az[m][tt][c] + bz);
                        float r = sigf(ar[m][tt][c] + br);
                        float hh = tanhf_(axh[m][tt][c] + bxh + r*(arh[m][tt][c] + brh));
                        float ho = hF1[row*HFS + uc];
                        float v  = z*ho + (1.f - z)*hh;
                        hF1[row*HFS + uc] = v;
                        hn[m][tt][c] = v;
                    }
            }
        {
            uint32_t* wp = (uint32_t*)hWf;
            #pragma unroll
            for (int m = 0; m < 2; m++)
                #pragma unroll
                for (int tt = 0; tt < 2; tt++)
                    #pragma unroll
                    for (int hi = 0; hi < 2; hi++)
                        wp[((m*L1_SLABS + warp)*32 + lr*4 + lc)*4 + tt*2 + hi]
                            = pack2(hn[m][tt][hi*2], hn[m][tt][hi*2 + 1]);
        }

        // ===== GEMM2a: h2_old @ U2 (L2 blob slabs 16..31) =====
        ZERO_ACC;
        #pragma unroll 4
        for (int s = 0; s < 16; s++){
            uint4 a0 = hA2u[s*32 + lane];
            uint4 a1 = hA2u[(16 + s)*32 + lane];
            const uint4* Bn = (s <= 13) ? (B2b + (18 + s)*1536)
                             : ((s == 14) ? B2b : (B2b + 1536));
            PF_STEP(cz, cr, ch, Bn);
            MMA_GATE(az,  cz, a0, a1);
            MMA_GATE(ar,  cr, a0, a1);
            MMA_GATE(arh, ch, a0, a1);
        }
        __syncthreads();                       // B1: h1_new visible

        // ===== GEMM2b: h1_new @ W2 (L2 blob slabs 0..15) =====
        #pragma unroll 4
        for (int s = 0; s < 16; s++){
            uint4 a0 = hAw[s*32 + lane];
            uint4 a1 = hAw[(L1_SLABS + s)*32 + lane];
            const uint4* Bn = (s <= 13) ? (B2b + (s+2)*1536)
                             : ((s == 14) ? B1b : (B1b + 1536));
            PF_STEP(cz, cr, ch, Bn);
            MMA_GATE(az,  cz, a0, a1);
            MMA_GATE(ar,  cr, a0, a1);
            MMA_GATE(axh, ch, a0, a1);
        }

        // ---- gate 2 + h2 store + pred partials ----
        float ps[4][5];
        #pragma unroll
        for (int ri = 0; ri < 4; ri++)
            #pragma unroll
            for (int o = 0; o < 5; o++) ps[ri][o] = 0.f;

        #pragma unroll
        for (int tt = 0; tt < 2; tt++)
            #pragma unroll
            for (int cc = 0; cc < 2; cc++){
                int uc = u0 + tt*8 + 2*lc + cc;
                float bz  = b2s[uc]       + b2s[G3 + uc];
                float br  = b2s[256 + uc] + b2s[G3 + 256 + uc];
                float bxh = b2s[512 + uc];
                float brh = b2s[G3 + 512 + uc];
                float wdv[5];
                #pragma unroll
                for (int o = 0; o < 5; o++) wdv[o] = wds[uc*5 + o];
                #pragma unroll
                for (int m = 0; m < 2; m++)
                    #pragma unroll
                    for (int hi = 0; hi < 2; hi++){
                        int c = hi*2 + cc;
                        int row = 16*m + lr + 8*hi;
                        float z = sigf(az[m][tt][c] + bz);
                        float r = sigf(ar[m][tt][c] + br);
                        float hh = tanhf_(axh[m][tt][c] + bxh + r*(arh[m][tt][c] + brh));
                        float ho = hF2[row*HFS + uc];
                        float v  = z*ho + (1.f - z)*hh;
                        hF2[row*HFS + uc] = v;
                        hn[m][tt][c] = v;
                        int ri = 2*m + hi;
                        #pragma unroll
                        for (int o = 0; o < 5; o++) ps[ri][o] += v * wdv[o];
                    }
            }
        {
            uint32_t* wp = (uint32_t*)(sm + OFF_HA2);
            #pragma unroll
            for (int m = 0; m < 2; m++)
                #pragma unroll
                for (int tt = 0; tt < 2; tt++)
                    #pragma unroll
                    for (int hi = 0; hi < 2; hi++)
                        wp[((m*16 + warp)*32 + lr*4 + lc)*4 + tt*2 + hi]
                            = pack2(hn[m][tt][hi*2], hn[m][tt][hi*2 + 1]);
        }
        #pragma unroll
        for (int ri = 0; ri < 4; ri++)
            #pragma unroll
            for (int o = 0; o < 5; o++){
                ps[ri][o] += __shfl_xor_sync(0xffffffffu, ps[ri][o], 1);
                ps[ri][o] += __shfl_xor_sync(0xffffffffu, ps[ri][o], 2);
            }
        if (lc == 0){
            #pragma unroll
            for (int ri = 0; ri < 4; ri++)
                #pragma unroll
                for (int o = 0; o < 5; o++)
                    part[warp*160 + (lr + 8*ri)*5 + o] = ps[ri][o];
        }
        __syncthreads();                       // B2

        // ---- tail: reduce, output, stage x_{t+1} ----
        if (tid < 160){
            int row = tid / 5, o = tid % 5;
            float s = bds[o];
            #pragma unroll
            for (int w = 0; w < 16; w++) s += part[w*160 + tid];
            int grow = row0 + row;
            int tout = (t < WARM) ? t : t + 1;
            out[(size_t)grow*960 + tout*5 + o] = s;
            if (t == WARM - 1) out[(size_t)grow*960 + WARM*5 + o] = s;
            if (t + 1 >= WARM && t + 1 < TSTEPS){
                int k = o + 1;
                int m = row >> 4, rr = row & 15, hh = rr >> 3, rl = rr & 7;
                __half* hp = (__half*)hWf;
                hp[(((m*L1_SLABS + 16)*32 + rl*4 + (k >> 1))*4 + hh)*2 + (k & 1)]
                    = __float2half_rn(s);
            }
        }
        if (tid < NROWS && t + 1 < TSTEPS){
            int row = tid;
            int m = row >> 4, rr = row & 15, hh = rr >> 3, rl = rr & 7;
            __half* hp = (__half*)hWf;
            if (t + 1 < WARM){
                const float* ip = inputs + ((size_t)(row0 + row)*192 + (t + 1))*6;
                #pragma unroll
                for (int k = 0; k < 6; k++)
                    hp[(((m*L1_SLABS + 16)*32 + rl*4 + (k >> 1))*4 + hh)*2 + (k & 1)]
                        = __float2half_rn(ip[k]);
            } else {
                float qv = qpre[row*127 + (t + 1 - WARM)];
                hp[(((m*L1_SLABS + 16)*32 + rl*4)*4 + hh)*2] = __float2half_rn(qv);
            }
        }
        __syncthreads();                       // B3: x_{t+1} visible
    }
}

// ---------------------------------------------------------------------------
extern "C" void kernel_launch(void* const* d_in, const int* in_sizes, int n_in,
                              void* d_out, int out_size) {
    (void)in_sizes; (void)n_in; (void)out_size;
    const float* inputs = (const float*)d_in[0];
    const float* W1 = (const float*)d_in[1];
    const float* U1 = (const float*)d_in[2];
    const float* b1 = (const float*)d_in[3];
    const float* W2 = (const float*)d_in[4];
    const float* U2 = (const float*)d_in[5];
    const float* b2 = (const float*)d_in[6];
    const float* Wd = (const float*)d_in[7];
    const float* bd = (const float*)d_in[8];
    float* out = (float*)d_out;

    cudaFuncSetAttribute(gru_kernel, cudaFuncAttributeMaxDynamicSharedMemorySize,
                         SMEM_BYTES);
    prep_kernel<<<(TOT_U4 + 255)/256, 256>>>(W1, U1, W2, U2);
    gru_kernel<<<NCTA, NTHREADS, SMEM_BYTES>>>(inputs, b1, b2, Wd, bd, out);
}